// round 1
// baseline (speedup 1.0000x reference)
#include <cuda_runtime.h>

#define NN   50000
#define NE   800000
#define EMB  64
#define FIN  32
#define SCALE_F 0.4251202479144762f

#define SCAN_BLK 1024
#define NBLK_SCAN ((NN + SCAN_BLK - 1) / SCAN_BLK)   // 49

// ---------------- device scratch (static allocation; no cudaMalloc) ----------------
__device__ float g_cons[NN * EMB];
__device__ float g_var [NN * EMB];
__device__ float g_u   [NN * EMB];
__device__ int   g_rowptr[NN + 1];
__device__ int   g_cursor[NN];          // doubles as degree histogram
__device__ int   g_csr_dst[NE];
__device__ float g_csr_w [NE];
__device__ float g_sumsq;
__device__ float g_inv_norm;
__device__ int   g_bsum[64];            // block sums for scan (49 used)

// ---------------- init: zero histogram + sumsq ----------------
__global__ void k_init() {
    int stride = gridDim.x * blockDim.x;
    for (int i = blockIdx.x * blockDim.x + threadIdx.x; i < NN; i += stride)
        g_cursor[i] = 0;
    if (blockIdx.x == 0 && threadIdx.x == 0) g_sumsq = 0.0f;
}

// ---------------- sum of squares of edge weights ----------------
__global__ void k_sumsq(const float* __restrict__ ew) {
    __shared__ float red[256];
    int t = threadIdx.x;
    float a = 0.0f;
    int stride = gridDim.x * blockDim.x;
    for (int e = blockIdx.x * blockDim.x + t; e < NE; e += stride) {
        float w = ew[e];
        a += w * w;
    }
    red[t] = a;
    __syncthreads();
    for (int off = 128; off > 0; off >>= 1) {
        if (t < off) red[t] += red[t + off];
        __syncthreads();
    }
    if (t == 0) atomicAdd(&g_sumsq, red[0]);
}

// ---------------- histogram of src ----------------
__global__ void k_hist(const int* __restrict__ ei) {
    int stride = gridDim.x * blockDim.x;
    for (int e = blockIdx.x * blockDim.x + threadIdx.x; e < NE; e += stride)
        atomicAdd(&g_cursor[ei[2 * e]], 1);
}

// ---------------- scan pass 1: per-block exclusive scan of degrees ----------------
__global__ void k_scan1() {
    __shared__ int s[SCAN_BLK];
    int t = threadIdx.x;
    int i = blockIdx.x * SCAN_BLK + t;
    int val = (i < NN) ? g_cursor[i] : 0;
    s[t] = val;
    __syncthreads();
    for (int off = 1; off < SCAN_BLK; off <<= 1) {
        int v = (t >= off) ? s[t - off] : 0;
        __syncthreads();
        s[t] += v;
        __syncthreads();
    }
    int incl = s[t];
    if (i < NN) g_rowptr[i] = incl - val;       // exclusive
    if (t == SCAN_BLK - 1) g_bsum[blockIdx.x] = incl;
}

// ---------------- scan pass 2: scan block sums (+ inv_norm) ----------------
__global__ void k_scan2() {
    __shared__ int s[64];
    int t = threadIdx.x;
    int val = (t < NBLK_SCAN) ? g_bsum[t] : 0;
    s[t] = val;
    __syncthreads();
    for (int off = 1; off < 64; off <<= 1) {
        int v = (t >= off) ? s[t - off] : 0;
        __syncthreads();
        s[t] += v;
        __syncthreads();
    }
    if (t < NBLK_SCAN) g_bsum[t] = s[t] - val;  // exclusive
    if (t == 0) g_inv_norm = 1.0f / sqrtf(g_sumsq);
}

// ---------------- scan pass 3: add block offsets, copy to cursor ----------------
__global__ void k_scan3() {
    int stride = gridDim.x * blockDim.x;
    for (int i = blockIdx.x * blockDim.x + threadIdx.x; i < NN; i += stride) {
        int r = g_rowptr[i] + g_bsum[i / SCAN_BLK];
        g_rowptr[i] = r;
        g_cursor[i] = r;
    }
    if (blockIdx.x == 0 && threadIdx.x == 0) g_rowptr[NN] = NE;
}

// ---------------- scatter edges into CSR (weights pre-normalized) ----------------
__global__ void k_scatter(const int* __restrict__ ei, const float* __restrict__ ew) {
    float inv = g_inv_norm;
    int stride = gridDim.x * blockDim.x;
    for (int e = blockIdx.x * blockDim.x + threadIdx.x; e < NE; e += stride) {
        int s = ei[2 * e];
        int d = ei[2 * e + 1];
        int slot = atomicAdd(&g_cursor[s], 1);
        g_csr_dst[slot] = d;
        g_csr_w [slot] = ew[e] * inv;
    }
}

// ---------------- input GEMM: out = relu(x @ W + b), x:[NN,32], W:[32,64] ----------------
__global__ void k_ingemm(const float* __restrict__ x, const float* __restrict__ W,
                         const float* __restrict__ bias, int which) {
    __shared__ float Ws[FIN * EMB];
    __shared__ float bs[EMB];
    __shared__ float xs[4][FIN];
    float* out = which ? g_var : g_cons;
    int tx = threadIdx.x, ty = threadIdx.y;
    int tid = ty * 64 + tx;
    for (int i = tid; i < FIN * EMB; i += 256) Ws[i] = W[i];
    if (tid < EMB) bs[tid] = bias[tid];
    int row = blockIdx.x * 4 + ty;                  // NN % 4 == 0 -> always valid
    if (tx < FIN) xs[ty][tx] = x[row * FIN + tx];
    __syncthreads();
    float acc = bs[tx];
#pragma unroll
    for (int k = 0; k < FIN; k++) acc = fmaf(xs[ty][k], Ws[k * EMB + tx], acc);
    out[row * EMB + tx] = fmaxf(acc, 0.0f);
}

// ---------------- fused SpMM(cons) + var update (c-to-v half layer) ----------------
// conv = sum_e w * cons[dst];  var = relu((var + t*(c - conv))*SCALE);  u = 2*var_new - var_old
__global__ void k_ctov(const float* __restrict__ c, const float* __restrict__ temps, int layer) {
    int warp = (blockIdx.x * blockDim.x + threadIdx.x) >> 5;   // row; grid sized exactly
    int lane = threadIdx.x & 31;
    float t = temps[layer * 2 + 1];
    int s = g_rowptr[warp], e = g_rowptr[warp + 1];
    const float2* F = reinterpret_cast<const float2*>(g_cons);
    float2 acc = make_float2(0.0f, 0.0f);
    int j = s;
    for (; j + 1 < e; j += 2) {
        int d0 = g_csr_dst[j];     float w0 = g_csr_w[j];
        int d1 = g_csr_dst[j + 1]; float w1 = g_csr_w[j + 1];
        float2 v0 = F[d0 * 32 + lane];
        float2 v1 = F[d1 * 32 + lane];
        acc.x = fmaf(w0, v0.x, acc.x); acc.y = fmaf(w0, v0.y, acc.y);
        acc.x = fmaf(w1, v1.x, acc.x); acc.y = fmaf(w1, v1.y, acc.y);
    }
    if (j < e) {
        int d0 = g_csr_dst[j]; float w0 = g_csr_w[j];
        float2 v0 = F[d0 * 32 + lane];
        acc.x = fmaf(w0, v0.x, acc.x); acc.y = fmaf(w0, v0.y, acc.y);
    }
    float cr = c[warp];
    float2* V = reinterpret_cast<float2*>(g_var);
    float2* U = reinterpret_cast<float2*>(g_u);
    float2 vo = V[warp * 32 + lane];
    float2 vn;
    vn.x = fmaxf((vo.x + t * (cr - acc.x)) * SCALE_F, 0.0f);
    vn.y = fmaxf((vo.y + t * (cr - acc.y)) * SCALE_F, 0.0f);
    V[warp * 32 + lane] = vn;
    U[warp * 32 + lane] = make_float2(2.0f * vn.x - vo.x, 2.0f * vn.y - vo.y);
}

// ---------------- fused SpMM(u) + cons update (v-to-c half layer) ----------------
// conv2 = sum_e w * u[dst];  cons = relu(cons - t*(b - conv2))
__global__ void k_vtoc(const float* __restrict__ b, const float* __restrict__ temps, int layer) {
    int warp = (blockIdx.x * blockDim.x + threadIdx.x) >> 5;
    int lane = threadIdx.x & 31;
    float t = temps[layer * 2 + 0];
    int s = g_rowptr[warp], e = g_rowptr[warp + 1];
    const float2* F = reinterpret_cast<const float2*>(g_u);
    float2 acc = make_float2(0.0f, 0.0f);
    int j = s;
    for (; j + 1 < e; j += 2) {
        int d0 = g_csr_dst[j];     float w0 = g_csr_w[j];
        int d1 = g_csr_dst[j + 1]; float w1 = g_csr_w[j + 1];
        float2 v0 = F[d0 * 32 + lane];
        float2 v1 = F[d1 * 32 + lane];
        acc.x = fmaf(w0, v0.x, acc.x); acc.y = fmaf(w0, v0.y, acc.y);
        acc.x = fmaf(w1, v1.x, acc.x); acc.y = fmaf(w1, v1.y, acc.y);
    }
    if (j < e) {
        int d0 = g_csr_dst[j]; float w0 = g_csr_w[j];
        float2 v0 = F[d0 * 32 + lane];
        acc.x = fmaf(w0, v0.x, acc.x); acc.y = fmaf(w0, v0.y, acc.y);
    }
    float br = b[warp];
    float2* C = reinterpret_cast<float2*>(g_cons);
    float2 co = C[warp * 32 + lane];
    float2 cn;
    cn.x = fmaxf(co.x - t * (br - acc.x), 0.0f);
    cn.y = fmaxf(co.y - t * (br - acc.y), 0.0f);
    C[warp * 32 + lane] = cn;
}

// ---------------- output head: out = relu(x @ W1 + b1) @ W2, per-row scalar ----------------
__global__ void k_out(const float* __restrict__ W1, const float* __restrict__ b1,
                      const float* __restrict__ W2, float* __restrict__ out, int src_sel) {
    __shared__ float W1s[EMB * EMB];
    __shared__ float b1s[EMB];
    __shared__ float W2s[EMB];
    __shared__ float xs[4][EMB];
    __shared__ float red[4][2];
    const float* x = src_sel ? g_cons : g_var;
    int tx = threadIdx.x, ty = threadIdx.y;
    int tid = ty * 64 + tx;
    for (int i = tid; i < EMB * EMB; i += 256) W1s[i] = W1[i];
    if (tid < EMB) { b1s[tid] = b1[tid]; W2s[tid] = W2[tid]; }
    int row = blockIdx.x * 4 + ty;                  // NN % 4 == 0
    xs[ty][tx] = x[row * EMB + tx];
    __syncthreads();
    float acc = b1s[tx];
#pragma unroll
    for (int k = 0; k < EMB; k++) acc = fmaf(xs[ty][k], W1s[k * EMB + tx], acc);
    float p = fmaxf(acc, 0.0f) * W2s[tx];
    // reduce over 64 threads = 2 hardware warps
#pragma unroll
    for (int off = 16; off > 0; off >>= 1)
        p += __shfl_down_sync(0xFFFFFFFFu, p, off);
    int lane = tx & 31;
    if (lane == 0) red[ty][tx >> 5] = p;
    __syncthreads();
    if (tx == 0) out[row] = red[ty][0] + red[ty][1];
}

// ---------------- launch ----------------
extern "C" void kernel_launch(void* const* d_in, const int* in_sizes, int n_in,
                              void* d_out, int out_size) {
    const float* con_feat   = (const float*)d_in[0];
    const float* var_feat   = (const float*)d_in[1];
    const float* edge_w     = (const float*)d_in[2];
    const float* c          = (const float*)d_in[3];
    const float* b          = (const float*)d_in[4];
    const float* W_cons     = (const float*)d_in[5];
    const float* b_cons     = (const float*)d_in[6];
    const float* W_var      = (const float*)d_in[7];
    const float* b_var      = (const float*)d_in[8];
    const float* temps_ctov = (const float*)d_in[9];
    const float* temps_vtoc = (const float*)d_in[10];
    const float* W1_o1      = (const float*)d_in[11];
    const float* b1_o1      = (const float*)d_in[12];
    const float* W2_o1      = (const float*)d_in[13];
    const float* W1_o2      = (const float*)d_in[14];
    const float* b1_o2      = (const float*)d_in[15];
    const float* W2_o2      = (const float*)d_in[16];
    const int*   edge_index = (const int*)d_in[17];
    float* out = (float*)d_out;

    dim3 b64x4(64, 4);

    k_init   <<<64, 256>>>();
    k_sumsq  <<<256, 256>>>(edge_w);
    k_hist   <<<512, 256>>>(edge_index);
    k_scan1  <<<NBLK_SCAN, SCAN_BLK>>>();
    k_scan2  <<<1, 64>>>();
    k_scan3  <<<(NN + 255) / 256, 256>>>();
    k_scatter<<<512, 256>>>(edge_index, edge_w);

    k_ingemm<<<NN / 4, b64x4>>>(con_feat, W_cons, b_cons, 0);
    k_ingemm<<<NN / 4, b64x4>>>(var_feat, W_var,  b_var,  1);

    for (int l = 0; l < 4; l++) {
        k_ctov<<<NN / 8, 256>>>(c, temps_ctov, l);   // 8 warps/block * 6250 = 50000 rows
        k_vtoc<<<NN / 8, 256>>>(b, temps_vtoc, l);
    }

    k_out<<<NN / 4, b64x4>>>(W1_o1, b1_o1, W2_o1, out,      0);  // out1 from var
    k_out<<<NN / 4, b64x4>>>(W1_o2, b1_o2, W2_o2, out + NN, 1);  // out2 from cons
}

// round 2
// speedup vs baseline: 1.2149x; 1.2149x over previous
#include <cuda_runtime.h>

#define NN   50000
#define NE   800000
#define EMB  64
#define FIN  32
#define SCALE_F 0.4251202479144762f

#define SCAN_BLK 1024
#define NBLK_SCAN ((NN + SCAN_BLK - 1) / SCAN_BLK)   // 49

// ---------------- device scratch (static allocation; no cudaMalloc) ----------------
__device__ float g_cons[NN * EMB];
__device__ float g_var [NN * EMB];
__device__ float g_u   [NN * EMB];
__device__ int   g_rowptr[NN + 1];
__device__ int   g_cursor[NN];          // doubles as degree histogram
__device__ int2  g_epack[NE];           // interleaved {dst, w-bits}
__device__ float g_part[256];           // per-block sumsq partials
__device__ float g_inv_norm;
__device__ int   g_bsum[64];            // block sums for scan (49 used)

// ---------------- init: zero histogram + partial sum of squares (no atomics) ----------------
__global__ void k_initsum(const float* __restrict__ ew) {
    int t = threadIdx.x;
    int stride = gridDim.x * blockDim.x;
    for (int i = blockIdx.x * blockDim.x + t; i < NN; i += stride)
        g_cursor[i] = 0;
    __shared__ float red[256];
    float a = 0.0f;
    for (int e = blockIdx.x * blockDim.x + t; e < NE; e += stride) {
        float w = ew[e];
        a = fmaf(w, w, a);
    }
    red[t] = a;
    __syncthreads();
    for (int off = 128; off > 0; off >>= 1) {
        if (t < off) red[t] += red[t + off];
        __syncthreads();
    }
    if (t == 0) g_part[blockIdx.x] = red[0];
}

// ---------------- histogram of src ----------------
__global__ void k_hist(const int* __restrict__ ei) {
    int stride = gridDim.x * blockDim.x;
    for (int e = blockIdx.x * blockDim.x + threadIdx.x; e < NE; e += stride)
        atomicAdd(&g_cursor[ei[2 * e]], 1);
}

// ---------------- scan pass 1: per-block exclusive scan of degrees ----------------
__global__ void k_scan1() {
    __shared__ int s[SCAN_BLK];
    int t = threadIdx.x;
    int i = blockIdx.x * SCAN_BLK + t;
    int val = (i < NN) ? g_cursor[i] : 0;
    s[t] = val;
    __syncthreads();
    for (int off = 1; off < SCAN_BLK; off <<= 1) {
        int v = (t >= off) ? s[t - off] : 0;
        __syncthreads();
        s[t] += v;
        __syncthreads();
    }
    int incl = s[t];
    if (i < NN) g_rowptr[i] = incl - val;       // exclusive
    if (t == SCAN_BLK - 1) g_bsum[blockIdx.x] = incl;
}

// ---------------- scan pass 2: scan block sums + finish sumsq -> inv_norm ----------------
__global__ void k_scan2() {
    __shared__ float fr[256];
    __shared__ int s[64];
    int t = threadIdx.x;
    fr[t] = g_part[t];
    __syncthreads();
    for (int off = 128; off > 0; off >>= 1) {
        if (t < off) fr[t] += fr[t + off];
        __syncthreads();
    }
    if (t == 0) g_inv_norm = 1.0f / sqrtf(fr[0]);

    int val = 0;
    if (t < 64) {
        val = (t < NBLK_SCAN) ? g_bsum[t] : 0;
        s[t] = val;
    }
    __syncthreads();
    for (int off = 1; off < 64; off <<= 1) {
        int v = 0;
        if (t < 64 && t >= off) v = s[t - off];
        __syncthreads();
        if (t < 64) s[t] += v;
        __syncthreads();
    }
    if (t < 64 && t < NBLK_SCAN) g_bsum[t] = s[t] - val;  // exclusive
}

// ---------------- scan pass 3: add block offsets, copy to cursor ----------------
__global__ void k_scan3() {
    int stride = gridDim.x * blockDim.x;
    for (int i = blockIdx.x * blockDim.x + threadIdx.x; i < NN; i += stride) {
        int r = g_rowptr[i] + g_bsum[i / SCAN_BLK];
        g_rowptr[i] = r;
        g_cursor[i] = r;
    }
    if (blockIdx.x == 0 && threadIdx.x == 0) g_rowptr[NN] = NE;
}

// ---------------- scatter edges into interleaved CSR (weights pre-normalized) ----------------
__global__ void k_scatter(const int* __restrict__ ei, const float* __restrict__ ew) {
    float inv = g_inv_norm;
    int stride = gridDim.x * blockDim.x;
    for (int e = blockIdx.x * blockDim.x + threadIdx.x; e < NE; e += stride) {
        int s = ei[2 * e];
        int d = ei[2 * e + 1];
        int slot = atomicAdd(&g_cursor[s], 1);
        g_epack[slot] = make_int2(d, __float_as_int(ew[e] * inv));
    }
}

// ---------------- input GEMM: out = relu(x @ W + b), 32 rows / block ----------------
__global__ void k_ingemm(const float* __restrict__ x, const float* __restrict__ W,
                         const float* __restrict__ bias, int which) {
    __shared__ float Ws[FIN * EMB];
    __shared__ float bs[EMB];
    __shared__ float xs[4][FIN];
    float* out = which ? g_var : g_cons;
    int tx = threadIdx.x, ty = threadIdx.y;
    int tid = ty * 64 + tx;
    for (int i = tid; i < FIN * EMB; i += 256) Ws[i] = W[i];
    if (tid < EMB) bs[tid] = bias[tid];
    __syncthreads();
    for (int it = 0; it < 8; it++) {
        int row = blockIdx.x * 32 + it * 4 + ty;
        if (row < NN && tx < FIN) xs[ty][tx] = x[row * FIN + tx];
        __syncthreads();
        if (row < NN) {
            float acc = bs[tx];
#pragma unroll
            for (int k = 0; k < FIN; k++) acc = fmaf(xs[ty][k], Ws[k * EMB + tx], acc);
            out[row * EMB + tx] = fmaxf(acc, 0.0f);
        }
        __syncthreads();
    }
}

// ---------------- SpMM core: one warp per row, coalesced edge load + shfl broadcast ----------------
__device__ __forceinline__ float2 spmm_row(const float2* __restrict__ F, int s, int e, int lane) {
    float ax = 0.0f, ay = 0.0f;
    for (int base = s; base < e; base += 32) {
        int k = base + lane;
        int di = 0; float wi = 0.0f;
        if (k < e) {
            int2 p = g_epack[k];
            di = p.x;
            wi = __int_as_float(p.y);
        }
        int cnt = min(e - base, 32);
        for (int t0 = 0; t0 < cnt; t0 += 8) {
#pragma unroll
            for (int q = 0; q < 8; q++) {
                int   d = __shfl_sync(0xFFFFFFFFu, di, t0 + q);
                float w = __shfl_sync(0xFFFFFFFFu, wi, t0 + q);
                float2 v = __ldg(&F[d * 32 + lane]);
                ax = fmaf(w, v.x, ax);
                ay = fmaf(w, v.y, ay);
            }
        }
    }
    return make_float2(ax, ay);
}

// ---------------- fused SpMM(cons) + var update (c-to-v half layer) ----------------
__global__ void k_ctov(const float* __restrict__ c, const float* __restrict__ temps, int layer) {
    int row  = (blockIdx.x * blockDim.x + threadIdx.x) >> 5;   // grid sized exactly
    int lane = threadIdx.x & 31;
    float t = __ldg(&temps[layer * 2 + 1]);
    int s = g_rowptr[row], e = g_rowptr[row + 1];
    float2 acc = spmm_row(reinterpret_cast<const float2*>(g_cons), s, e, lane);
    float cr = __ldg(&c[row]);
    float2* V = reinterpret_cast<float2*>(g_var);
    float2* U = reinterpret_cast<float2*>(g_u);
    float2 vo = V[row * 32 + lane];
    float2 vn;
    vn.x = fmaxf((vo.x + t * (cr - acc.x)) * SCALE_F, 0.0f);
    vn.y = fmaxf((vo.y + t * (cr - acc.y)) * SCALE_F, 0.0f);
    V[row * 32 + lane] = vn;
    U[row * 32 + lane] = make_float2(2.0f * vn.x - vo.x, 2.0f * vn.y - vo.y);
}

// ---------------- fused SpMM(u) + cons update (v-to-c half layer) ----------------
__global__ void k_vtoc(const float* __restrict__ b, const float* __restrict__ temps, int layer) {
    int row  = (blockIdx.x * blockDim.x + threadIdx.x) >> 5;
    int lane = threadIdx.x & 31;
    float t = __ldg(&temps[layer * 2 + 0]);
    int s = g_rowptr[row], e = g_rowptr[row + 1];
    float2 acc = spmm_row(reinterpret_cast<const float2*>(g_u), s, e, lane);
    float br = __ldg(&b[row]);
    float2* C = reinterpret_cast<float2*>(g_cons);
    float2 co = C[row * 32 + lane];
    float2 cn;
    cn.x = fmaxf(co.x - t * (br - acc.x), 0.0f);
    cn.y = fmaxf(co.y - t * (br - acc.y), 0.0f);
    C[row * 32 + lane] = cn;
}

// ---------------- output head: out = relu(x @ W1 + b1) @ W2, 32 rows / block ----------------
__global__ void k_out(const float* __restrict__ W1, const float* __restrict__ b1,
                      const float* __restrict__ W2, float* __restrict__ out, int src_sel) {
    __shared__ float W1s[EMB * EMB];
    __shared__ float b1s[EMB];
    __shared__ float W2s[EMB];
    __shared__ float xs[4][EMB];
    __shared__ float red[4][2];
    const float* x = src_sel ? g_cons : g_var;
    int tx = threadIdx.x, ty = threadIdx.y;
    int tid = ty * 64 + tx;
    for (int i = tid; i < EMB * EMB; i += 256) W1s[i] = W1[i];
    if (tid < EMB) { b1s[tid] = b1[tid]; W2s[tid] = W2[tid]; }
    __syncthreads();
    for (int it = 0; it < 8; it++) {
        int row = blockIdx.x * 32 + it * 4 + ty;
        if (row < NN) xs[ty][tx] = x[row * EMB + tx];
        __syncthreads();
        if (row < NN) {
            float acc = b1s[tx];
#pragma unroll
            for (int k = 0; k < EMB; k++) acc = fmaf(xs[ty][k], W1s[k * EMB + tx], acc);
            float p = fmaxf(acc, 0.0f) * W2s[tx];
#pragma unroll
            for (int off = 16; off > 0; off >>= 1)
                p += __shfl_down_sync(0xFFFFFFFFu, p, off);
            if ((tx & 31) == 0) red[ty][tx >> 5] = p;
        }
        __syncthreads();
        if (row < NN && tx == 0) out[row] = red[ty][0] + red[ty][1];
        __syncthreads();
    }
}

// ---------------- launch ----------------
extern "C" void kernel_launch(void* const* d_in, const int* in_sizes, int n_in,
                              void* d_out, int out_size) {
    const float* con_feat   = (const float*)d_in[0];
    const float* var_feat   = (const float*)d_in[1];
    const float* edge_w     = (const float*)d_in[2];
    const float* c          = (const float*)d_in[3];
    const float* b          = (const float*)d_in[4];
    const float* W_cons     = (const float*)d_in[5];
    const float* b_cons     = (const float*)d_in[6];
    const float* W_var      = (const float*)d_in[7];
    const float* b_var      = (const float*)d_in[8];
    const float* temps_ctov = (const float*)d_in[9];
    const float* temps_vtoc = (const float*)d_in[10];
    const float* W1_o1      = (const float*)d_in[11];
    const float* b1_o1      = (const float*)d_in[12];
    const float* W2_o1      = (const float*)d_in[13];
    const float* W1_o2      = (const float*)d_in[14];
    const float* b1_o2      = (const float*)d_in[15];
    const float* W2_o2      = (const float*)d_in[16];
    const int*   edge_index = (const int*)d_in[17];
    float* out = (float*)d_out;

    dim3 b64x4(64, 4);
    int gemm_grid = (NN + 31) / 32;

    k_initsum<<<256, 256>>>(edge_w);
    k_hist   <<<512, 256>>>(edge_index);
    k_scan1  <<<NBLK_SCAN, SCAN_BLK>>>();
    k_ingemm <<<gemm_grid, b64x4>>>(con_feat, W_cons, b_cons, 0);
    k_scan2  <<<1, 256>>>();
    k_ingemm <<<gemm_grid, b64x4>>>(var_feat, W_var, b_var, 1);
    k_scan3  <<<(NN + 255) / 256, 256>>>();
    k_scatter<<<512, 256>>>(edge_index, edge_w);

    for (int l = 0; l < 4; l++) {
        k_ctov<<<NN / 8, 256>>>(c, temps_ctov, l);   // 8 warps/block * 6250 blocks = 50000 rows
        k_vtoc<<<NN / 8, 256>>>(b, temps_vtoc, l);
    }

    k_out<<<gemm_grid, b64x4>>>(W1_o1, b1_o1, W2_o1, out,      0);  // out1 from var
    k_out<<<gemm_grid, b64x4>>>(W1_o2, b1_o2, W2_o2, out + NN, 1);  // out2 from cons
}